// round 8
// baseline (speedup 1.0000x reference)
#include <cuda_runtime.h>
#include <math.h>

// Shapes (fixed by the problem)
#define B 32
#define C 256
#define H 64
#define W 64
#define HW (H*W)            // 4096
#define PLANES (B*C)        // 8192
#define RH 3                // int(0.05*64)
#define RW 6                // int(0.1*64)
#define CLAMP_SX 61.0f      // h - rh
#define CLAMP_SY 58.0f      // w - rw

// Scratch (no cudaMalloc allowed). Zero-initialized at load; the MLP block
// resets its batch counter after use, so graph replays start clean.
__device__ float g_mean[PLANES];
__device__ float g_scale[PLANES];
__device__ int   g_sx[PLANES];
__device__ int   g_sy[PLANES];
__device__ int   g_ctr[B];

__device__ __forceinline__ float sigmoidf_acc(float v) {
    return 1.0f / (1.0f + expf(-v));
}
__device__ __forceinline__ float warp_red(float s) {
#pragma unroll
    for (int o = 16; o; o >>= 1) s += __shfl_xor_sync(0xffffffffu, s, o);
    return s;
}

// ---------------------------------------------------------------------------
// Kernel 1: per-plane mean; the LAST block of each batch (by arrival counter)
// additionally runs the whole batch MLP inline (8 warps, coalesced
// warp-reductions). No spinning anywhere — pure signal-then-work.
// ---------------------------------------------------------------------------
__global__ void __launch_bounds__(256) k_mean_mlp(
    const float* __restrict__ x,
    const float* __restrict__ se_w1,   // (16,256)
    const float* __restrict__ se_w2,   // (256,16)
    const float* __restrict__ ch_w, const float* __restrict__ ch_b,
    const float* __restrict__ cw_w, const float* __restrict__ cw_b,
    const float* __restrict__ dh_fc1w, const float* __restrict__ dh_fc1b,
    const float* __restrict__ dh_fc2w, const float* __restrict__ dh_fc2b,
    const float* __restrict__ dw_fc1w, const float* __restrict__ dw_fc1b,
    const float* __restrict__ dw_fc2w, const float* __restrict__ dw_fc2b)
{
    const int plane = blockIdx.x;
    const int batch = plane >> 8;        // plane / 256
    const int tid   = threadIdx.x;
    const int wid   = tid >> 5;          // 0..7
    const int lane  = tid & 31;

    // ---- mean over this plane ----
    {
        const float4* xp = reinterpret_cast<const float4*>(x) + (size_t)plane * (HW / 4);
        float s = 0.f;
#pragma unroll
        for (int i = 0; i < 4; i++) {
            float4 v = xp[tid + i * 256];
            s += (v.x + v.y) + (v.z + v.w);
        }
        s = warp_red(s);
        __shared__ float ws[8];
        if (lane == 0) ws[wid] = s;
        __syncthreads();
        if (tid == 0) {
            float t = 0.f;
#pragma unroll
            for (int i = 0; i < 8; i++) t += ws[i];
            g_mean[plane] = t * (1.0f / (float)HW);
        }
    }

    // ---- arrival counter: last block of the batch runs the MLP ----
    __shared__ int isLast;
    if (tid == 0) {
        __threadfence();                       // release g_mean[plane]
        int old = atomicAdd(&g_ctr[batch], 1);
        isLast = (old == C - 1);
    }
    __syncthreads();
    if (!isLast) return;
    __threadfence();                           // acquire all batch means

    // ---- batch MLP with 8 warps ----
    __shared__ float yv[256];
    __shared__ float t1[16];
    __shared__ float gv[256];
    __shared__ float vh[256];
    __shared__ float th1[64];
    __shared__ float th2[1024];

    yv[tid] = g_mean[batch * 256 + tid];
    __syncthreads();

    float yreg[8];
#pragma unroll
    for (int k = 0; k < 8; k++) yreg[k] = yv[lane + k * 32];

    // SE squeeze: 2 outputs per warp
#pragma unroll
    for (int i = 0; i < 2; i++) {
        int o = wid * 2 + i;
        const float* r = se_w1 + o * 256;
        float s = 0.f;
#pragma unroll
        for (int k = 0; k < 8; k++) s = fmaf(yreg[k], r[lane + k * 32], s);
        s = warp_red(s);
        if (lane == 0) t1[o] = fmaxf(s, 0.f);
    }
    __syncthreads();

    // SE excite: scale + gated mean
    {
        const float4* r = reinterpret_cast<const float4*>(se_w2 + tid * 16);
        const float4* tt = reinterpret_cast<const float4*>(t1);
        float s = 0.f;
#pragma unroll
        for (int j = 0; j < 4; j++) {
            float4 wv = r[j], tv = tt[j];
            s = fmaf(wv.x, tv.x, fmaf(wv.y, tv.y, fmaf(wv.z, tv.z, fmaf(wv.w, tv.w, s))));
        }
        float sg = sigmoidf_acc(s);
        g_scale[batch * 256 + tid] = sg;
        gv[tid] = yv[tid] * sg;
    }
    __syncthreads();

    float greg[8];
#pragma unroll
    for (int k = 0; k < 8; k++) greg[k] = gv[lane + k * 32];

    // Two dyrelu branches, sequential
    for (int br = 0; br < 2; br++) {
        const float* cw   = br ? cw_w    : ch_w;
        const float* cb   = br ? cw_b    : ch_b;
        const float* fc1w = br ? dw_fc1w : dh_fc1w;
        const float* fc1b = br ? dw_fc1b : dh_fc1b;
        const float* fc2w = br ? dw_fc2w : dh_fc2w;
        const float* fc2b = br ? dw_fc2b : dh_fc2b;
        int* outArr  = br ? g_sy : g_sx;
        float clampv = br ? CLAMP_SY : CLAMP_SX;

        // vh[256] = gv @ cw^T + cb : 32 outputs per warp
#pragma unroll 4
        for (int i = 0; i < 32; i++) {
            int o = wid * 32 + i;
            const float* r = cw + o * 256;
            float s = 0.f;
#pragma unroll
            for (int k = 0; k < 8; k++) s = fmaf(greg[k], r[lane + k * 32], s);
            s = warp_red(s);
            if (lane == 0) vh[o] = s + cb[o];
        }
        __syncthreads();

        float vreg[8];
#pragma unroll
        for (int k = 0; k < 8; k++) vreg[k] = vh[lane + k * 32];

        // th1[64] = relu(vh @ fc1w^T + fc1b) : 8 outputs per warp
#pragma unroll
        for (int i = 0; i < 8; i++) {
            int o = wid * 8 + i;
            const float* r = fc1w + o * 256;
            float s = 0.f;
#pragma unroll
            for (int k = 0; k < 8; k++) s = fmaf(vreg[k], r[lane + k * 32], s);
            s = warp_red(s);
            if (lane == 0) th1[o] = fmaxf(s + fc1b[o], 0.f);
        }
        __syncthreads();

        float t1a = th1[lane * 2];
        float t1b = th1[lane * 2 + 1];

        // th2[1024] = fc2(th1) : 128 outputs per warp (unroll to overlap SHFLs)
#pragma unroll 8
        for (int i = 0; i < 128; i++) {
            int m = wid * 128 + i;
            float2 wv = reinterpret_cast<const float2*>(fc2w + m * 64)[lane];
            float s = fmaf(t1a, wv.x, t1b * wv.y);
            s = warp_red(s);
            if (lane == 0) th2[m] = s + fc2b[m];
        }
        __syncthreads();

        // per-channel dyrelu + sigmoid + ceil/clamp
        {
            float v  = vh[tid];
            float u0 = 2.0f * sigmoidf_acc(th2[tid * 4 + 0]) - 1.0f;
            float u1 = 2.0f * sigmoidf_acc(th2[tid * 4 + 1]) - 1.0f;
            float u2 = 2.0f * sigmoidf_acc(th2[tid * 4 + 2]) - 1.0f;
            float u3 = 2.0f * sigmoidf_acc(th2[tid * 4 + 3]) - 1.0f;
            float a0 = u0 + 1.0f, a1 = u1;
            float b0 = 0.5f * u2, b1 = 0.5f * u3;
            float dy = fmaxf(fmaf(v, a0, b0), fmaf(v, a1, b1));
            float sg = sigmoidf_acc(dy);
            outArr[batch * 256 + tid] = (int)fminf(ceilf(64.0f * sg), clampv);
        }
        __syncthreads();
    }

    // reset counter for next graph replay (only this block touches it now)
    if (tid == 0) g_ctr[batch] = 0;
}

// ---------------------------------------------------------------------------
// Kernel 2: out = x * scale * !inside.
// 512 threads, 4 planes per block (2048 blocks). Each thread front-batches
// 8 streaming float4 loads (high MLP_p1 for latency hiding), then masks and
// streams 8 stores. x and out are never reused -> __ldcs/__stcs.
// ---------------------------------------------------------------------------
__global__ void __launch_bounds__(512) k_apply(const float* __restrict__ x,
                                               float* __restrict__ out) {
    const int sub = threadIdx.x >> 7;        // 0..3: which plane in this block
    const int t   = threadIdx.x & 127;       // 0..127 within plane
    const int plane = blockIdx.x * 4 + sub;

    const float sc = g_scale[plane];
    const int sx = g_sx[plane];
    const int sy = g_sy[plane];

    const float4* xp = reinterpret_cast<const float4*>(x) + (size_t)plane * (HW / 4);
    float4* op = reinterpret_cast<float4*>(out) + (size_t)plane * (HW / 4);

    float4 v[8];
#pragma unroll
    for (int i = 0; i < 8; i++) v[i] = __ldcs(xp + t + i * 128);

#pragma unroll
    for (int i = 0; i < 8; i++) {
        int p = t + i * 128;        // float4 index within plane
        int row = p >> 4;           // (p*4) / 64
        int col = (p & 15) * 4;     // (p*4) % 64
        v[i].x *= sc; v[i].y *= sc; v[i].z *= sc; v[i].w *= sc;
        if (row >= sx && row < sx + RH) {
            if (col + 0 >= sy && col + 0 < sy + RW) v[i].x = 0.f;
            if (col + 1 >= sy && col + 1 < sy + RW) v[i].y = 0.f;
            if (col + 2 >= sy && col + 2 < sy + RW) v[i].z = 0.f;
            if (col + 3 >= sy && col + 3 < sy + RW) v[i].w = 0.f;
        }
        __stcs(op + p, v[i]);
    }
}

// ---------------------------------------------------------------------------
extern "C" void kernel_launch(void* const* d_in, const int* in_sizes, int n_in,
                              void* d_out, int out_size) {
    const float* x       = (const float*)d_in[0];
    const float* se_w1   = (const float*)d_in[1];
    const float* se_w2   = (const float*)d_in[2];
    const float* ch_w    = (const float*)d_in[3];
    const float* ch_b    = (const float*)d_in[4];
    const float* cw_w    = (const float*)d_in[5];
    const float* cw_b    = (const float*)d_in[6];
    const float* dh_fc1w = (const float*)d_in[7];
    const float* dh_fc1b = (const float*)d_in[8];
    const float* dh_fc2w = (const float*)d_in[9];
    const float* dh_fc2b = (const float*)d_in[10];
    const float* dw_fc1w = (const float*)d_in[11];
    const float* dw_fc1b = (const float*)d_in[12];
    const float* dw_fc2w = (const float*)d_in[13];
    const float* dw_fc2b = (const float*)d_in[14];
    float* out = (float*)d_out;

    k_mean_mlp<<<PLANES, 256>>>(x,
                                se_w1, se_w2, ch_w, ch_b, cw_w, cw_b,
                                dh_fc1w, dh_fc1b, dh_fc2w, dh_fc2b,
                                dw_fc1w, dw_fc1b, dw_fc2w, dw_fc2b);
    k_apply<<<PLANES / 4, 512>>>(x, out);
}

// round 9
// speedup vs baseline: 1.4213x; 1.4213x over previous
#include <cuda_runtime.h>
#include <math.h>

// Shapes (fixed by the problem)
#define B 32
#define C 256
#define H 64
#define W 64
#define HW (H*W)            // 4096
#define PLANES (B*C)        // 8192
#define RH 3                // int(0.05*64)
#define RW 6                // int(0.1*64)
#define CLAMP_SX 61.0f      // h - rh
#define CLAMP_SY 58.0f      // w - rw

// Scratch (no cudaMalloc allowed)
__device__ float g_mean[PLANES];
__device__ float g_scale[PLANES];
__device__ int   g_sx[PLANES];
__device__ int   g_sy[PLANES];

// ---------------------------------------------------------------------------
// Kernel 1: per-(b,c) mean of x over the 4096-element plane.
// One block per plane, 256 threads, float4 loads. Lean: 24 regs, high occ.
// ---------------------------------------------------------------------------
__global__ void __launch_bounds__(256) k_mean(const float* __restrict__ x) {
    int plane = blockIdx.x;
    const float4* xp = reinterpret_cast<const float4*>(x) + (size_t)plane * (HW / 4);
    int tid = threadIdx.x;

    float s = 0.f;
#pragma unroll
    for (int i = 0; i < 4; i++) {
        float4 v = xp[tid + i * 256];
        s += (v.x + v.y) + (v.z + v.w);
    }
#pragma unroll
    for (int o = 16; o; o >>= 1) s += __shfl_xor_sync(0xffffffffu, s, o);

    __shared__ float ws[8];
    if ((tid & 31) == 0) ws[tid >> 5] = s;
    __syncthreads();
    if (tid == 0) {
        float t = 0.f;
#pragma unroll
        for (int i = 0; i < 8; i++) t += ws[i];
        g_mean[plane] = t * (1.0f / (float)HW);
    }
}

// ---------------------------------------------------------------------------
// Kernel 2: MLP math, warp-per-output reductions, 512 threads = 16 warps.
// grid = (B, 2): blockIdx.x = batch, blockIdx.y = branch (0=h, 1=w).
// ---------------------------------------------------------------------------
__device__ __forceinline__ float sigmoidf_acc(float v) {
    return 1.0f / (1.0f + expf(-v));
}

__device__ __forceinline__ float warp_red(float s) {
#pragma unroll
    for (int o = 16; o; o >>= 1) s += __shfl_xor_sync(0xffffffffu, s, o);
    return s;
}

__global__ void __launch_bounds__(512) k_mlp(
    const float* __restrict__ se_w1,   // (16,256)
    const float* __restrict__ se_w2,   // (256,16)
    const float* __restrict__ ch_w, const float* __restrict__ ch_b,
    const float* __restrict__ cw_w, const float* __restrict__ cw_b,
    const float* __restrict__ dh_fc1w, const float* __restrict__ dh_fc1b,
    const float* __restrict__ dh_fc2w, const float* __restrict__ dh_fc2b,
    const float* __restrict__ dw_fc1w, const float* __restrict__ dw_fc1b,
    const float* __restrict__ dw_fc2w, const float* __restrict__ dw_fc2b)
{
    __shared__ float y[256];
    __shared__ float t1[16];
    __shared__ float gv[256];
    __shared__ float vh[256];
    __shared__ float th1[64];
    __shared__ float th2[1024];

    int b    = blockIdx.x;
    int br   = blockIdx.y;
    int tid  = threadIdx.x;
    int wid  = tid >> 5;          // 0..15
    int lane = tid & 31;

    const float* cw   = br ? cw_w    : ch_w;
    const float* cb   = br ? cw_b    : ch_b;
    const float* fc1w = br ? dw_fc1w : dh_fc1w;
    const float* fc1b = br ? dw_fc1b : dh_fc1b;
    const float* fc2w = br ? dw_fc2w : dh_fc2w;
    const float* fc2b = br ? dw_fc2b : dh_fc2b;
    int* outArr = br ? g_sy : g_sx;
    float clampv = br ? CLAMP_SY : CLAMP_SX;

    if (tid < 256) y[tid] = g_mean[b * 256 + tid];
    __syncthreads();

    float yreg[8];
#pragma unroll
    for (int k = 0; k < 8; k++) yreg[k] = y[lane + k * 32];

    // SE squeeze: 1 output per warp
    {
        const float* r = se_w1 + wid * 256;
        float s = 0.f;
#pragma unroll
        for (int k = 0; k < 8; k++) s = fmaf(yreg[k], r[lane + k * 32], s);
        s = warp_red(s);
        if (lane == 0) t1[wid] = fmaxf(s, 0.f);
    }
    __syncthreads();

    // SE excite
    if (tid < 256) {
        const float4* r = reinterpret_cast<const float4*>(se_w2 + tid * 16);
        const float4* t = reinterpret_cast<const float4*>(t1);
        float s = 0.f;
#pragma unroll
        for (int j = 0; j < 4; j++) {
            float4 wv = r[j];
            float4 tv = t[j];
            s = fmaf(wv.x, tv.x, fmaf(wv.y, tv.y, fmaf(wv.z, tv.z, fmaf(wv.w, tv.w, s))));
        }
        float sg = sigmoidf_acc(s);
        if (br == 0) g_scale[b * 256 + tid] = sg;
        gv[tid] = y[tid] * sg;
    }
    __syncthreads();

    float greg[8];
#pragma unroll
    for (int k = 0; k < 8; k++) greg[k] = gv[lane + k * 32];

    // vh[256] = gv @ cw^T + cb : 16 outputs per warp
#pragma unroll 4
    for (int i = 0; i < 16; i++) {
        int o = wid * 16 + i;
        const float* r = cw + o * 256;
        float s = 0.f;
#pragma unroll
        for (int k = 0; k < 8; k++) s = fmaf(greg[k], r[lane + k * 32], s);
        s = warp_red(s);
        if (lane == 0) vh[o] = s + cb[o];
    }
    __syncthreads();

    float vreg[8];
#pragma unroll
    for (int k = 0; k < 8; k++) vreg[k] = vh[lane + k * 32];

    // th1[64] = relu(vh @ fc1w^T + fc1b) : 4 outputs per warp
#pragma unroll
    for (int i = 0; i < 4; i++) {
        int o = wid * 4 + i;
        const float* r = fc1w + o * 256;
        float s = 0.f;
#pragma unroll
        for (int k = 0; k < 8; k++) s = fmaf(vreg[k], r[lane + k * 32], s);
        s = warp_red(s);
        if (lane == 0) th1[o] = fmaxf(s + fc1b[o], 0.f);
    }
    __syncthreads();

    float t1a = th1[lane * 2];
    float t1b = th1[lane * 2 + 1];

    // th2[1024] = fc2(th1): 64 outputs per warp
#pragma unroll 8
    for (int i = 0; i < 64; i++) {
        int m = wid * 64 + i;
        float2 wv = reinterpret_cast<const float2*>(fc2w + m * 64)[lane];
        float s = fmaf(t1a, wv.x, t1b * wv.y);
        s = warp_red(s);
        if (lane == 0) th2[m] = s + fc2b[m];
    }
    __syncthreads();

    // dyrelu + sigmoid + ceil/clamp
    if (tid < 256) {
        float v = vh[tid];
        float u0 = 2.0f * sigmoidf_acc(th2[tid * 4 + 0]) - 1.0f;
        float u1 = 2.0f * sigmoidf_acc(th2[tid * 4 + 1]) - 1.0f;
        float u2 = 2.0f * sigmoidf_acc(th2[tid * 4 + 2]) - 1.0f;
        float u3 = 2.0f * sigmoidf_acc(th2[tid * 4 + 3]) - 1.0f;
        float a0 = u0 + 1.0f, a1 = u1;
        float b0 = 0.5f * u2, b1 = 0.5f * u3;
        float dy = fmaxf(fmaf(v, a0, b0), fmaf(v, a1, b1));
        float sg = sigmoidf_acc(dy);
        outArr[b * 256 + tid] = (int)fminf(ceilf(64.0f * sg), clampv);
    }
}

// ---------------------------------------------------------------------------
// Kernel 3: out = x * scale * !inside. (R8 version, measured 36.2us / 74% DRAM)
// 512 threads, 4 planes per block. Each thread front-batches 8 streaming
// float4 loads (high MLP_p1), then masks and streams 8 stores.
// ---------------------------------------------------------------------------
__global__ void __launch_bounds__(512) k_apply(const float* __restrict__ x,
                                               float* __restrict__ out) {
    const int sub = threadIdx.x >> 7;        // 0..3: which plane in this block
    const int t   = threadIdx.x & 127;       // 0..127 within plane
    const int plane = blockIdx.x * 4 + sub;

    const float sc = g_scale[plane];
    const int sx = g_sx[plane];
    const int sy = g_sy[plane];

    const float4* xp = reinterpret_cast<const float4*>(x) + (size_t)plane * (HW / 4);
    float4* op = reinterpret_cast<float4*>(out) + (size_t)plane * (HW / 4);

    float4 v[8];
#pragma unroll
    for (int i = 0; i < 8; i++) v[i] = __ldcs(xp + t + i * 128);

#pragma unroll
    for (int i = 0; i < 8; i++) {
        int p = t + i * 128;        // float4 index within plane
        int row = p >> 4;           // (p*4) / 64
        int col = (p & 15) * 4;     // (p*4) % 64
        v[i].x *= sc; v[i].y *= sc; v[i].z *= sc; v[i].w *= sc;
        if (row >= sx && row < sx + RH) {
            if (col + 0 >= sy && col + 0 < sy + RW) v[i].x = 0.f;
            if (col + 1 >= sy && col + 1 < sy + RW) v[i].y = 0.f;
            if (col + 2 >= sy && col + 2 < sy + RW) v[i].z = 0.f;
            if (col + 3 >= sy && col + 3 < sy + RW) v[i].w = 0.f;
        }
        __stcs(op + p, v[i]);
    }
}

// ---------------------------------------------------------------------------
extern "C" void kernel_launch(void* const* d_in, const int* in_sizes, int n_in,
                              void* d_out, int out_size) {
    const float* x       = (const float*)d_in[0];
    const float* se_w1   = (const float*)d_in[1];
    const float* se_w2   = (const float*)d_in[2];
    const float* ch_w    = (const float*)d_in[3];
    const float* ch_b    = (const float*)d_in[4];
    const float* cw_w    = (const float*)d_in[5];
    const float* cw_b    = (const float*)d_in[6];
    const float* dh_fc1w = (const float*)d_in[7];
    const float* dh_fc1b = (const float*)d_in[8];
    const float* dh_fc2w = (const float*)d_in[9];
    const float* dh_fc2b = (const float*)d_in[10];
    const float* dw_fc1w = (const float*)d_in[11];
    const float* dw_fc1b = (const float*)d_in[12];
    const float* dw_fc2w = (const float*)d_in[13];
    const float* dw_fc2b = (const float*)d_in[14];
    float* out = (float*)d_out;

    k_mean<<<PLANES, 256>>>(x);
    dim3 mg(B, 2);
    k_mlp<<<mg, 512>>>(se_w1, se_w2, ch_w, ch_b, cw_w, cw_b,
                       dh_fc1w, dh_fc1b, dh_fc2w, dh_fc2b,
                       dw_fc1w, dw_fc1b, dw_fc2w, dw_fc2b);
    k_apply<<<PLANES / 4, 512>>>(x, out);
}

// round 10
// speedup vs baseline: 1.6663x; 1.1724x over previous
#include <cuda_runtime.h>
#include <math.h>

// Shapes (fixed by the problem)
#define B 32
#define C 256
#define H 64
#define W 64
#define HW (H*W)            // 4096
#define PLANES (B*C)        // 8192
#define RH 3                // int(0.05*64)
#define RW 6                // int(0.1*64)
#define CLAMP_SX 61.0f      // h - rh
#define CLAMP_SY 58.0f      // w - rw

#define QUARTERS 4          // fc2/final split factor for k_mlp

// Scratch (no cudaMalloc allowed)
__device__ float g_mean[PLANES];
__device__ float g_scale[PLANES];
__device__ int   g_sx[PLANES];
__device__ int   g_sy[PLANES];

// ---------------------------------------------------------------------------
// Kernel 1: per-(b,c) mean of x over the 4096-element plane.
// One block per plane, 256 threads, float4 loads. Lean: 24 regs, high occ.
// ---------------------------------------------------------------------------
__global__ void __launch_bounds__(256) k_mean(const float* __restrict__ x) {
    int plane = blockIdx.x;
    const float4* xp = reinterpret_cast<const float4*>(x) + (size_t)plane * (HW / 4);
    int tid = threadIdx.x;

    float s = 0.f;
#pragma unroll
    for (int i = 0; i < 4; i++) {
        float4 v = xp[tid + i * 256];
        s += (v.x + v.y) + (v.z + v.w);
    }
#pragma unroll
    for (int o = 16; o; o >>= 1) s += __shfl_xor_sync(0xffffffffu, s, o);

    __shared__ float ws[8];
    if ((tid & 31) == 0) ws[tid >> 5] = s;
    __syncthreads();
    if (tid == 0) {
        float t = 0.f;
#pragma unroll
        for (int i = 0; i < 8; i++) t += ws[i];
        g_mean[plane] = t * (1.0f / (float)HW);
    }
}

// ---------------------------------------------------------------------------
// Kernel 2: MLP math. grid = (B, 2, QUARTERS): batch, branch, fc2-quarter.
// Each block redundantly computes SE + vh + th1 (cheap, runs in parallel on
// idle SMs), then computes only ITS quarter of fc2 (16 outputs/warp) and the
// final dyrelu for its quarter of channels. 256 blocks -> real latency hiding.
// ---------------------------------------------------------------------------
__device__ __forceinline__ float sigmoidf_acc(float v) {
    return 1.0f / (1.0f + expf(-v));
}

__device__ __forceinline__ float warp_red(float s) {
#pragma unroll
    for (int o = 16; o; o >>= 1) s += __shfl_xor_sync(0xffffffffu, s, o);
    return s;
}

__global__ void __launch_bounds__(512) k_mlp(
    const float* __restrict__ se_w1,   // (16,256)
    const float* __restrict__ se_w2,   // (256,16)
    const float* __restrict__ ch_w, const float* __restrict__ ch_b,
    const float* __restrict__ cw_w, const float* __restrict__ cw_b,
    const float* __restrict__ dh_fc1w, const float* __restrict__ dh_fc1b,
    const float* __restrict__ dh_fc2w, const float* __restrict__ dh_fc2b,
    const float* __restrict__ dw_fc1w, const float* __restrict__ dw_fc1b,
    const float* __restrict__ dw_fc2w, const float* __restrict__ dw_fc2b)
{
    __shared__ float y[256];
    __shared__ float t1[16];
    __shared__ float gv[256];
    __shared__ float vh[256];
    __shared__ float th1[64];
    __shared__ float th2[256];    // this block's quarter of fc2 outputs

    int b    = blockIdx.x;
    int br   = blockIdx.y;
    int q    = blockIdx.z;        // fc2 quarter 0..3
    int tid  = threadIdx.x;
    int wid  = tid >> 5;          // 0..15
    int lane = tid & 31;

    const float* cw   = br ? cw_w    : ch_w;
    const float* cb   = br ? cw_b    : ch_b;
    const float* fc1w = br ? dw_fc1w : dh_fc1w;
    const float* fc1b = br ? dw_fc1b : dh_fc1b;
    const float* fc2w = br ? dw_fc2w : dh_fc2w;
    const float* fc2b = br ? dw_fc2b : dh_fc2b;
    int* outArr = br ? g_sy : g_sx;
    float clampv = br ? CLAMP_SY : CLAMP_SX;

    if (tid < 256) y[tid] = g_mean[b * 256 + tid];
    __syncthreads();

    float yreg[8];
#pragma unroll
    for (int k = 0; k < 8; k++) yreg[k] = y[lane + k * 32];

    // SE squeeze: 1 output per warp
    {
        const float* r = se_w1 + wid * 256;
        float s = 0.f;
#pragma unroll
        for (int k = 0; k < 8; k++) s = fmaf(yreg[k], r[lane + k * 32], s);
        s = warp_red(s);
        if (lane == 0) t1[wid] = fmaxf(s, 0.f);
    }
    __syncthreads();

    // SE excite
    if (tid < 256) {
        const float4* r = reinterpret_cast<const float4*>(se_w2 + tid * 16);
        const float4* t = reinterpret_cast<const float4*>(t1);
        float s = 0.f;
#pragma unroll
        for (int j = 0; j < 4; j++) {
            float4 wv = r[j];
            float4 tv = t[j];
            s = fmaf(wv.x, tv.x, fmaf(wv.y, tv.y, fmaf(wv.z, tv.z, fmaf(wv.w, tv.w, s))));
        }
        float sg = sigmoidf_acc(s);
        if (br == 0 && q == 0) g_scale[b * 256 + tid] = sg;
        gv[tid] = y[tid] * sg;
    }
    __syncthreads();

    float greg[8];
#pragma unroll
    for (int k = 0; k < 8; k++) greg[k] = gv[lane + k * 32];

    // vh[256] = gv @ cw^T + cb : 16 outputs per warp (deep unroll for MLP)
#pragma unroll 8
    for (int i = 0; i < 16; i++) {
        int o = wid * 16 + i;
        const float* r = cw + o * 256;
        float s = 0.f;
#pragma unroll
        for (int k = 0; k < 8; k++) s = fmaf(greg[k], r[lane + k * 32], s);
        s = warp_red(s);
        if (lane == 0) vh[o] = s + cb[o];
    }
    __syncthreads();

    float vreg[8];
#pragma unroll
    for (int k = 0; k < 8; k++) vreg[k] = vh[lane + k * 32];

    // th1[64] = relu(vh @ fc1w^T + fc1b) : 4 outputs per warp
#pragma unroll
    for (int i = 0; i < 4; i++) {
        int o = wid * 4 + i;
        const float* r = fc1w + o * 256;
        float s = 0.f;
#pragma unroll
        for (int k = 0; k < 8; k++) s = fmaf(vreg[k], r[lane + k * 32], s);
        s = warp_red(s);
        if (lane == 0) th1[o] = fmaxf(s + fc1b[o], 0.f);
    }
    __syncthreads();

    float t1a = th1[lane * 2];
    float t1b = th1[lane * 2 + 1];

    // th2 quarter: outputs m in [q*256, q*256+256), 16 per warp
#pragma unroll 8
    for (int i = 0; i < 16; i++) {
        int m = q * 256 + wid * 16 + i;
        float2 wv = reinterpret_cast<const float2*>(fc2w + m * 64)[lane];
        float s = fmaf(t1a, wv.x, t1b * wv.y);
        s = warp_red(s);
        if (lane == 0) th2[wid * 16 + i] = s + fc2b[m];
    }
    __syncthreads();

    // dyrelu + sigmoid + ceil/clamp for this quarter's 64 channels
    if (tid < 64) {
        int c = q * 64 + tid;            // global channel
        float v = vh[c];
        float u0 = 2.0f * sigmoidf_acc(th2[tid * 4 + 0]) - 1.0f;
        float u1 = 2.0f * sigmoidf_acc(th2[tid * 4 + 1]) - 1.0f;
        float u2 = 2.0f * sigmoidf_acc(th2[tid * 4 + 2]) - 1.0f;
        float u3 = 2.0f * sigmoidf_acc(th2[tid * 4 + 3]) - 1.0f;
        float a0 = u0 + 1.0f, a1 = u1;
        float b0 = 0.5f * u2, b1 = 0.5f * u3;
        float dy = fmaxf(fmaf(v, a0, b0), fmaf(v, a1, b1));
        float sg = sigmoidf_acc(dy);
        outArr[b * 256 + c] = (int)fminf(ceilf(64.0f * sg), clampv);
    }
}

// ---------------------------------------------------------------------------
// Kernel 3: out = x * scale * !inside. (measured 36.2us / 74% DRAM)
// 512 threads, 4 planes per block. Each thread front-batches 8 streaming
// float4 loads (high MLP_p1), then masks and streams 8 stores.
// ---------------------------------------------------------------------------
__global__ void __launch_bounds__(512) k_apply(const float* __restrict__ x,
                                               float* __restrict__ out) {
    const int sub = threadIdx.x >> 7;        // 0..3: which plane in this block
    const int t   = threadIdx.x & 127;       // 0..127 within plane
    const int plane = blockIdx.x * 4 + sub;

    const float sc = g_scale[plane];
    const int sx = g_sx[plane];
    const int sy = g_sy[plane];

    const float4* xp = reinterpret_cast<const float4*>(x) + (size_t)plane * (HW / 4);
    float4* op = reinterpret_cast<float4*>(out) + (size_t)plane * (HW / 4);

    float4 v[8];
#pragma unroll
    for (int i = 0; i < 8; i++) v[i] = __ldcs(xp + t + i * 128);

#pragma unroll
    for (int i = 0; i < 8; i++) {
        int p = t + i * 128;        // float4 index within plane
        int row = p >> 4;           // (p*4) / 64
        int col = (p & 15) * 4;     // (p*4) % 64
        v[i].x *= sc; v[i].y *= sc; v[i].z *= sc; v[i].w *= sc;
        if (row >= sx && row < sx + RH) {
            if (col + 0 >= sy && col + 0 < sy + RW) v[i].x = 0.f;
            if (col + 1 >= sy && col + 1 < sy + RW) v[i].y = 0.f;
            if (col + 2 >= sy && col + 2 < sy + RW) v[i].z = 0.f;
            if (col + 3 >= sy && col + 3 < sy + RW) v[i].w = 0.f;
        }
        __stcs(op + p, v[i]);
    }
}

// ---------------------------------------------------------------------------
extern "C" void kernel_launch(void* const* d_in, const int* in_sizes, int n_in,
                              void* d_out, int out_size) {
    const float* x       = (const float*)d_in[0];
    const float* se_w1   = (const float*)d_in[1];
    const float* se_w2   = (const float*)d_in[2];
    const float* ch_w    = (const float*)d_in[3];
    const float* ch_b    = (const float*)d_in[4];
    const float* cw_w    = (const float*)d_in[5];
    const float* cw_b    = (const float*)d_in[6];
    const float* dh_fc1w = (const float*)d_in[7];
    const float* dh_fc1b = (const float*)d_in[8];
    const float* dh_fc2w = (const float*)d_in[9];
    const float* dh_fc2b = (const float*)d_in[10];
    const float* dw_fc1w = (const float*)d_in[11];
    const float* dw_fc1b = (const float*)d_in[12];
    const float* dw_fc2w = (const float*)d_in[13];
    const float* dw_fc2b = (const float*)d_in[14];
    float* out = (float*)d_out;

    k_mean<<<PLANES, 256>>>(x);
    dim3 mg(B, 2, QUARTERS);
    k_mlp<<<mg, 512>>>(se_w1, se_w2, ch_w, ch_b, cw_w, cw_b,
                       dh_fc1w, dh_fc1b, dh_fc2w, dh_fc2b,
                       dw_fc1w, dw_fc1b, dw_fc2w, dw_fc2b);
    k_apply<<<PLANES / 4, 512>>>(x, out);
}